// round 15
// baseline (speedup 1.0000x reference)
#include <cuda_runtime.h>
#include <cuda_bf16.h>
#include <cuda_fp16.h>
#include <cstdint>
#include <math.h>

#define S_LEN 4096
#define HDIM  2048
#define NHEADS 16
#define HD    128
#define SCALE 0.08838834764831845f
#define SCALE2 0.1275332511737922f   // SCALE * log2(e)

// ---------------- scratch globals ----------------
__device__ __half g_H[S_LEN * HDIM];
__device__ __half g_Wq[HDIM * HDIM], g_Wk[HDIM * HDIM];
__device__ __half g_Wv[HDIM * HDIM], g_Wo[HDIM * HDIM];
__device__ __half g_Qh[S_LEN * HDIM], g_Ql[S_LEN * HDIM];
__device__ __half g_Kh[S_LEN * HDIM];
__device__ __half g_Vh[S_LEN * HDIM];
__device__ __half g_VTh[HDIM * S_LEN];
__device__ __half g_O[S_LEN * HDIM];

// ---------------- helpers ----------------
__device__ __forceinline__ uint32_t smem_u32(const void* p) {
    uint32_t a;
    asm("{ .reg .u64 t; cvta.to.shared.u64 t, %1; cvt.u32.u64 %0, t; }"
        : "=r"(a) : "l"(p));
    return a;
}
__device__ __forceinline__ void ldsm4(uint32_t* r, uint32_t a) {
    asm volatile("ldmatrix.sync.aligned.m8n8.x4.shared.b16 {%0,%1,%2,%3}, [%4];"
        : "=r"(r[0]), "=r"(r[1]), "=r"(r[2]), "=r"(r[3]) : "r"(a));
}
__device__ __forceinline__ void mma_f16(float* c, const uint32_t* a,
                                        const uint32_t* b) {
    asm volatile("mma.sync.aligned.m16n8k16.row.col.f32.f16.f16.f32 "
        "{%0,%1,%2,%3}, {%4,%5,%6,%7}, {%8,%9}, {%0,%1,%2,%3};"
        : "+f"(c[0]), "+f"(c[1]), "+f"(c[2]), "+f"(c[3])
        : "r"(a[0]), "r"(a[1]), "r"(a[2]), "r"(a[3]), "r"(b[0]), "r"(b[1]));
}
__device__ __forceinline__ float ex2f(float x) {
    float r;
    asm("ex2.approx.f32 %0, %1;" : "=f"(r) : "f"(x));
    return r;
}
__device__ __forceinline__ void split_store2h(__half* hi, __half* lo,
                                              float x, float y) {
    __half hx = __float2half_rn(x), hy = __float2half_rn(y);
    __half2 h2 = __halves2half2(hx, hy);
    __half2 l2 = __halves2half2(__float2half_rn(x - __half2float(hx)),
                                __float2half_rn(y - __half2float(hy)));
    *reinterpret_cast<__half2*>(hi) = h2;
    *reinterpret_cast<__half2*>(lo) = l2;
}
__device__ __forceinline__ uint32_t pack2h(float x, float y) {
    __half hx = __float2half_rn(x), hy = __float2half_rn(y);
    uint16_t a = *(uint16_t*)&hx, b = *(uint16_t*)&hy;
    return (uint32_t)a | ((uint32_t)b << 16);
}
#define CP_ASYNC16(dst, src) \
    asm volatile("cp.async.cg.shared.global [%0], [%1], 16;\n" \
                 :: "r"(dst), "l"(src))
#define CP_COMMIT asm volatile("cp.async.commit_group;\n" ::: "memory")
#define CP_WAIT0  asm volatile("cp.async.wait_group 0;\n" ::: "memory")
#define CP_WAIT1  asm volatile("cp.async.wait_group 1;\n" ::: "memory")

// ---------------- prepass: fp32 -> fp16 ----------------
__global__ __launch_bounds__(256) void conv_fp16(
    const float* __restrict__ in, __half* __restrict__ out, int n4)
{
    int i = blockIdx.x * blockDim.x + threadIdx.x;
    if (i < n4) {
        float4 v = ((const float4*)in)[i];
        *(__half2*)(out + i * 4) =
            __halves2half2(__float2half_rn(v.x), __float2half_rn(v.y));
        *(__half2*)(out + i * 4 + 2) =
            __halves2half2(__float2half_rn(v.z), __float2half_rn(v.w));
    }
}
__global__ __launch_bounds__(256) void conv_fp16_w4(
    const float* __restrict__ w0, const float* __restrict__ w1,
    const float* __restrict__ w2, const float* __restrict__ w3,
    __half* __restrict__ o0, __half* __restrict__ o1,
    __half* __restrict__ o2, __half* __restrict__ o3, int n4)
{
    const float* src = (blockIdx.y == 0) ? w0 : (blockIdx.y == 1) ? w1
                       : (blockIdx.y == 2) ? w2 : w3;
    __half* dst = (blockIdx.y == 0) ? o0 : (blockIdx.y == 1) ? o1
                  : (blockIdx.y == 2) ? o2 : o3;
    int i = blockIdx.x * blockDim.x + threadIdx.x;
    if (i < n4) {
        float4 v = ((const float4*)src)[i];
        *(__half2*)(dst + i * 4) =
            __halves2half2(__float2half_rn(v.x), __float2half_rn(v.y));
        *(__half2*)(dst + i * 4 + 2) =
            __halves2half2(__float2half_rn(v.z), __float2half_rn(v.w));
    }
}

// ---- HMMA GEMM v3: BM=BN=128, BK=32, 128 threads (2x2 warps, 64x64 tile),
//      3-stage cp.async, 2 CTAs/SM.
#define LDAB 40
#define G_BOFF 10240
#define STG_BYTES 20480               /* A 10240 + B 10240 */
#define GEMM_SMEM (3 * STG_BYTES)     /* 61440 */

template <int OUT_MODE>
__global__ __launch_bounds__(128, 2) void gemm_hmma(
    const __half* __restrict__ A, const __half* __restrict__ B,
    const float* __restrict__ bias, float scale,
    float* __restrict__ Cf, __half* __restrict__ Chh,
    __half* __restrict__ Chl, __half* __restrict__ Ch,
    int M, int N, int K)
{
    extern __shared__ char smraw[];
    const uint32_t sb = smem_u32(smraw);

    const int tid = threadIdx.x, lane = tid & 31, wid = tid >> 5;
    const int wm = wid >> 1, wn = wid & 1;           // 2 x 2 warps
    const int bm = blockIdx.y * 128, bn = blockIdx.x * 128;
    const int m0 = wm * 64, n0 = wn * 64;

    const int a_r = lane & 15, a_c = (lane >> 4) * 8;
    const int b_n = ((lane >> 4) & 1) * 8 + (lane & 7);
    const int b_k = ((lane >> 3) & 1) * 8;

    float acc[4][8][4];
#pragma unroll
    for (int mt = 0; mt < 4; mt++)
#pragma unroll
        for (int nt = 0; nt < 8; nt++)
#pragma unroll
            for (int j = 0; j < 4; j++) acc[mt][nt][j] = 0.f;

    const int nIter = K / 32;

    auto load_stage = [&](int kc, int s) {
        const uint32_t st = sb + s * STG_BYTES;
        const int k0 = kc * 32;
        const __half* ap = A + (size_t)(bm + tid) * K + k0;
        const __half* bp = B + (size_t)(bn + tid) * K + k0;
#pragma unroll
        for (int j = 0; j < 4; j++) {
            CP_ASYNC16(st + (tid * LDAB + j * 8) * 2, ap + j * 8);
            CP_ASYNC16(st + G_BOFF + (tid * LDAB + j * 8) * 2, bp + j * 8);
        }
        CP_COMMIT;
    };

    load_stage(0, 0);
    load_stage(1, 1);
    for (int kc = 0; kc < nIter; kc++) {
        CP_WAIT1;
        __syncthreads();
        if (kc + 2 < nIter) load_stage(kc + 2, (kc + 2) % 3);

        const uint32_t st = sb + (kc % 3) * STG_BYTES;
#pragma unroll
        for (int ks = 0; ks < 2; ks++) {
            const int k0 = ks * 16;
            uint32_t ah[4][4], bb[4][4];
#pragma unroll
            for (int mt = 0; mt < 4; mt++) {
                int off = ((m0 + mt * 16 + a_r) * LDAB + k0 + a_c) * 2;
                ldsm4(ah[mt], st + off);
            }
#pragma unroll
            for (int bp = 0; bp < 4; bp++) {
                int off = ((n0 + bp * 16 + b_n) * LDAB + k0 + b_k) * 2;
                ldsm4(bb[bp], st + G_BOFF + off);
            }
#pragma unroll
            for (int mt = 0; mt < 4; mt++)
#pragma unroll
                for (int nt = 0; nt < 8; nt++)
                    mma_f16(acc[mt][nt], ah[mt], &bb[nt >> 1][(nt & 1) * 2]);
        }
    }

#pragma unroll
    for (int mt = 0; mt < 4; mt++) {
        const int r0 = bm + m0 + mt * 16 + (lane >> 2);
#pragma unroll
        for (int nt = 0; nt < 8; nt++) {
            const int col = bn + n0 + nt * 8 + (lane & 3) * 2;
            float2 bv = *(const float2*)(bias + col);
            float c00 = (acc[mt][nt][0] + bv.x) * scale;
            float c01 = (acc[mt][nt][1] + bv.y) * scale;
            float c10 = (acc[mt][nt][2] + bv.x) * scale;
            float c11 = (acc[mt][nt][3] + bv.y) * scale;
            if (OUT_MODE == 0) {
                *(float2*)(Cf + (size_t)r0 * N + col) = make_float2(c00, c01);
                *(float2*)(Cf + (size_t)(r0 + 8) * N + col) = make_float2(c10, c11);
            } else if (OUT_MODE == 1) {
                split_store2h(Chh + (size_t)r0 * N + col,
                              Chl + (size_t)r0 * N + col, c00, c01);
                split_store2h(Chh + (size_t)(r0 + 8) * N + col,
                              Chl + (size_t)(r0 + 8) * N + col, c10, c11);
            } else {
                *(uint32_t*)(Ch + (size_t)r0 * N + col) = pack2h(c00, c01);
                *(uint32_t*)(Ch + (size_t)(r0 + 8) * N + col) = pack2h(c10, c11);
            }
        }
    }
}

// ------- transpose fp16: out[c][s] = in[s][c] -------
__global__ __launch_bounds__(256) void transpose_h(
    const __half* __restrict__ in, __half* __restrict__ out)
{
    __shared__ __half tile[32][34];
    const int cb = blockIdx.x * 32, sbk = blockIdx.y * 32;
    const int tx = threadIdx.x, ty = threadIdx.y;
#pragma unroll
    for (int j = 0; j < 4; j++)
        tile[ty + j * 8][tx] = in[(size_t)(sbk + ty + j * 8) * HDIM + cb + tx];
    __syncthreads();
#pragma unroll
    for (int j = 0; j < 4; j++)
        out[(size_t)(cb + ty + j * 8) * S_LEN + sbk + tx] = tile[tx][ty + j * 8];
}

// ---------------- fp16 flash attention v2: 64-query CTAs, 128 threads ----
// warp w owns rows [w*16, w*16+16). 64-key tiles, 2-stage cp.async.
// smem (elems): Qh 0 (64*136=8704) | Ql 8704 | stages at 17408, each 17920:
//   K +0 (64*136), V +8704 (128*72). Total (17408+2*17920)*2 = 106496 B.
#define LDQ 136
#define LDV 72
#define AQL 8704
#define ASTG0 17408
#define ASTG  17920
#define AVH_OFF 8704
#define ATT_SMEM 106496

__global__ __launch_bounds__(128, 2) void attn_hmma(
    const __half* __restrict__ Qhi, const __half* __restrict__ Qlo,
    const __half* __restrict__ Kh, const __half* __restrict__ VTh,
    __half* __restrict__ O)
{
    extern __shared__ __half smh[];
    const uint32_t sb = smem_u32(smh);

    const int tid = threadIdx.x, lane = tid & 31, wid = tid >> 5;
    const int qb = blockIdx.x * 64, h = blockIdx.y;

    const int a_r = lane & 15, a_c = (lane >> 4) * 8;
    const int b_n = ((lane >> 4) & 1) * 8 + (lane & 7);
    const int b_k = ((lane >> 3) & 1) * 8;
    const int qrow = wid * 16;

    const int k_r = tid >> 1, k_c = (tid & 1) * 64;   // K: 64 rows, 2 thr/row
    const int v_r = tid;                               // V: 128 rows, 1 thr/row

    auto load_kv = [&](int t, int s) {
        const uint32_t stg = sb + (ASTG0 + s * ASTG) * 2;
        const __half* kp = Kh + (size_t)(t * 64 + k_r) * HDIM + h * HD + k_c;
#pragma unroll
        for (int j = 0; j < 8; j++)
            CP_ASYNC16(stg + (k_r * LDQ + k_c + j * 8) * 2, kp + j * 8);
        const __half* vp = VTh + (size_t)(h * HD + v_r) * S_LEN + t * 64;
#pragma unroll
        for (int j = 0; j < 8; j++)
            CP_ASYNC16(stg + (AVH_OFF + v_r * LDV + j * 8) * 2, vp + j * 8);
        CP_COMMIT;
    };

    {
        const int r = tid >> 1, cs = (tid & 1) * 64;
        const __half* qh = Qhi + (size_t)(qb + r) * HDIM + h * HD + cs;
        const __half* ql = Qlo + (size_t)(qb + r) * HDIM + h * HD + cs;
#pragma unroll
        for (int j = 0; j < 8; j++) {
            CP_ASYNC16(sb + (r * LDQ + cs + j * 8) * 2, qh + j * 8);
            CP_ASYNC16(sb + (AQL + r * LDQ + cs + j * 8) * 2, ql + j * 8);
        }
        CP_COMMIT;          // group: Q
    }
    load_kv(0, 0);          // group: KV(0)

    CP_WAIT1;
    __syncthreads();

    uint32_t qfh[8][4], qfl[8][4];
#pragma unroll
    for (int ks = 0; ks < 8; ks++) {
        int off = ((qrow + a_r) * LDQ + ks * 16 + a_c) * 2;
        ldsm4(qfh[ks], sb + off);
        ldsm4(qfl[ks], sb + AQL * 2 + off);
    }

    float m0 = -INFINITY, m1 = -INFINITY, l0 = 0.f, l1 = 0.f;
    float oacc[16][4];
#pragma unroll
    for (int nt = 0; nt < 16; nt++)
#pragma unroll
        for (int j = 0; j < 4; j++) oacc[nt][j] = 0.f;

    const int NT = S_LEN / 64;
    for (int t = 0; t < NT; t++) {
        const int s = t & 1;
        CP_WAIT0;
        __syncthreads();
        if (t + 1 < NT) load_kv(t + 1, s ^ 1);

        const uint32_t stg = sb + (ASTG0 + s * ASTG) * 2;

        // ---- Phase 1: S = Q K^T (2 MMAs, Q hi/lo exact) ----
        float sacc[8][4];
#pragma unroll
        for (int nt = 0; nt < 8; nt++)
#pragma unroll
            for (int j = 0; j < 4; j++) sacc[nt][j] = 0.f;

#pragma unroll
        for (int ks = 0; ks < 8; ks++) {
            const int k0 = ks * 16;
            uint32_t bh[4][4];
#pragma unroll
            for (int g = 0; g < 4; g++) {
                int off = ((g * 16 + b_n) * LDQ + k0 + b_k) * 2;
                ldsm4(bh[g], stg + off);
            }
#pragma unroll
            for (int nt = 0; nt < 8; nt++) {
                const uint32_t* bhp = &bh[nt >> 1][(nt & 1) * 2];
                mma_f16(sacc[nt], qfh[ks], bhp);
                mma_f16(sacc[nt], qfl[ks], bhp);
            }
        }

        // ---- warp-local online softmax (log2 domain) ----
        float tm0 = -INFINITY, tm1 = -INFINITY;
#pragma unroll
        for (int nt = 0; nt < 8; nt++) {
            tm0 = fmaxf(tm0, fmaxf(sacc[nt][0], sacc[nt][1]));
            tm1 = fmaxf(tm1, fmaxf(sacc[nt][2], sacc[nt][3]));
        }
        tm0 = fmaxf(tm0, __shfl_xor_sync(0xffffffffu, tm0, 1));
        tm0 = fmaxf(tm0, __shfl_xor_sync(0xffffffffu, tm0, 2));
        tm1 = fmaxf(tm1, __shfl_xor_sync(0xffffffffu, tm1, 1));
        tm1 = fmaxf(tm1, __shfl_xor_sync(0xffffffffu, tm1, 2));
        const float mn0 = fmaxf(m0, tm0), mn1 = fmaxf(m1, tm1);
        const float c0 = ex2f(m0 - mn0), c1 = ex2f(m1 - mn1);
        m0 = mn0; m1 = mn1;

        float ls0 = 0.f, ls1 = 0.f;
#pragma unroll
        for (int nt = 0; nt < 8; nt++) {
            sacc[nt][0] = ex2f(sacc[nt][0] - mn0);
            sacc[nt][1] = ex2f(sacc[nt][1] - mn0);
            sacc[nt][2] = ex2f(sacc[nt][2] - mn1);
            sacc[nt][3] = ex2f(sacc[nt][3] - mn1);
            ls0 += sacc[nt][0] + sacc[nt][1];
            ls1 += sacc[nt][2] + sacc[nt][3];
        }
        ls0 += __shfl_xor_sync(0xffffffffu, ls0, 1);
        ls0 += __shfl_xor_sync(0xffffffffu, ls0, 2);
        ls1 += __shfl_xor_sync(0xffffffffu, ls1, 1);
        ls1 += __shfl_xor_sync(0xffffffffu, ls1, 2);
        l0 = l0 * c0 + ls0;
        l1 = l1 * c1 + ls1;

        if (c0 != 1.f || c1 != 1.f) {
#pragma unroll
            for (int nt = 0; nt < 16; nt++) {
                oacc[nt][0] *= c0; oacc[nt][1] *= c0;
                oacc[nt][2] *= c1; oacc[nt][3] *= c1;
            }
        }

        // ---- Phase 2: O += P V (single fp16 P) ----
#pragma unroll
        for (int ks = 0; ks < 4; ks++) {
            uint32_t p4[4];
            p4[0] = pack2h(sacc[2 * ks][0], sacc[2 * ks][1]);
            p4[1] = pack2h(sacc[2 * ks][2], sacc[2 * ks][3]);
            p4[2] = pack2h(sacc[2 * ks + 1][0], sacc[2 * ks + 1][1]);
            p4[3] = pack2h(sacc[2 * ks + 1][2], sacc[2 * ks + 1][3]);
            const int k0 = ks * 16;
#pragma unroll
            for (int g = 0; g < 8; g++) {
                uint32_t vh[4];
                int off = ((g * 16 + b_n) * LDV + k0 + b_k) * 2;
                ldsm4(vh, stg + AVH_OFF * 2 + off);
                mma_f16(oacc[g * 2 + 0], p4, &vh[0]);
                mma_f16(oacc[g * 2 + 1], p4, &vh[2]);
            }
        }
    }

    // ---- epilogue ----
    const float inv0 = 1.f / l0, inv1 = 1.f / l1;
    const int r0 = qrow + (lane >> 2);
#pragma unroll
    for (int nt = 0; nt < 16; nt++) {
        const int col = nt * 8 + (lane & 3) * 2;
        size_t i0 = (size_t)(qb + r0) * HDIM + h * HD + col;
        size_t i1 = (size_t)(qb + r0 + 8) * HDIM + h * HD + col;
        *(uint32_t*)(O + i0) = pack2h(oacc[nt][0] * inv0, oacc[nt][1] * inv0);
        *(uint32_t*)(O + i1) = pack2h(oacc[nt][2] * inv1, oacc[nt][3] * inv1);
    }
}

// ---------------- launch ----------------
extern "C" void kernel_launch(void* const* d_in, const int* in_sizes, int n_in,
                              void* d_out, int out_size)
{
    const float* hidden = (const float*)d_in[0];
    const float* Wq = (const float*)d_in[1];
    const float* bq = (const float*)d_in[2];
    const float* Wk = (const float*)d_in[3];
    const float* bk = (const float*)d_in[4];
    const float* Wv = (const float*)d_in[5];
    const float* bv = (const float*)d_in[6];
    const float* Wo = (const float*)d_in[7];
    const float* bo = (const float*)d_in[8];
    float* out = (float*)d_out;

    __half *Hp, *Wqp, *Wkp, *Wvp, *Wop, *Qh, *Ql, *Kh, *Vh, *VTh, *Op;
    cudaGetSymbolAddress((void**)&Hp, g_H);
    cudaGetSymbolAddress((void**)&Wqp, g_Wq);   cudaGetSymbolAddress((void**)&Wkp, g_Wk);
    cudaGetSymbolAddress((void**)&Wvp, g_Wv);   cudaGetSymbolAddress((void**)&Wop, g_Wo);
    cudaGetSymbolAddress((void**)&Qh, g_Qh);    cudaGetSymbolAddress((void**)&Ql, g_Ql);
    cudaGetSymbolAddress((void**)&Kh, g_Kh);    cudaGetSymbolAddress((void**)&Vh, g_Vh);
    cudaGetSymbolAddress((void**)&VTh, g_VTh);
    cudaGetSymbolAddress((void**)&Op, g_O);

    cudaFuncSetAttribute(gemm_hmma<0>, cudaFuncAttributeMaxDynamicSharedMemorySize, GEMM_SMEM);
    cudaFuncSetAttribute(gemm_hmma<1>, cudaFuncAttributeMaxDynamicSharedMemorySize, GEMM_SMEM);
    cudaFuncSetAttribute(gemm_hmma<2>, cudaFuncAttributeMaxDynamicSharedMemorySize, GEMM_SMEM);
    cudaFuncSetAttribute(attn_hmma, cudaFuncAttributeMaxDynamicSharedMemorySize, ATT_SMEM);

    const int nH4 = S_LEN * HDIM / 4, nW4 = HDIM * HDIM / 4;
    conv_fp16<<<nH4 / 256, 256>>>(hidden, Hp, nH4);
    conv_fp16_w4<<<dim3(nW4 / 256, 4), 256>>>(Wq, Wk, Wv, Wo,
                                              Wqp, Wkp, Wvp, Wop, nW4);

    dim3 ggrid(HDIM / 128, S_LEN / 128);   // (16, 32) = 512 CTAs
    gemm_hmma<1><<<ggrid, 128, GEMM_SMEM>>>(Hp, Wqp, bq, SCALE2,
                                            nullptr, Qh, Ql, nullptr,
                                            S_LEN, HDIM, HDIM);
    gemm_hmma<2><<<ggrid, 128, GEMM_SMEM>>>(Hp, Wkp, bk, 1.f,
                                            nullptr, nullptr, nullptr, Kh,
                                            S_LEN, HDIM, HDIM);
    gemm_hmma<2><<<ggrid, 128, GEMM_SMEM>>>(Hp, Wvp, bv, 1.f,
                                            nullptr, nullptr, nullptr, Vh,
                                            S_LEN, HDIM, HDIM);

    dim3 tgrid(HDIM / 32, S_LEN / 32);
    transpose_h<<<tgrid, dim3(32, 8)>>>(Vh, VTh);

    dim3 agrid(S_LEN / 64, NHEADS);        // (64, 16) = 1024 CTAs
    attn_hmma<<<agrid, 128, ATT_SMEM>>>(Qh, Ql, Kh, VTh, Op);

    gemm_hmma<0><<<ggrid, 128, GEMM_SMEM>>>(Op, Wop, bo, 1.f,
                                            out, nullptr, nullptr, nullptr,
                                            S_LEN, HDIM, HDIM);
}

// round 16
// speedup vs baseline: 1.1163x; 1.1163x over previous
#include <cuda_runtime.h>
#include <cuda_bf16.h>
#include <cuda_fp16.h>
#include <cstdint>
#include <math.h>

#define S_LEN 4096
#define HDIM  2048
#define NHEADS 16
#define HD    128
#define SCALE 0.08838834764831845f
#define SCALE2 0.1275332511737922f   // SCALE * log2(e)

// ---------------- scratch globals ----------------
__device__ __half g_H[S_LEN * HDIM];
__device__ __half g_Wq[HDIM * HDIM], g_Wk[HDIM * HDIM];
__device__ __half g_Wv[HDIM * HDIM], g_Wo[HDIM * HDIM];
__device__ __half g_Qh[S_LEN * HDIM], g_Ql[S_LEN * HDIM];
__device__ __half g_Kh[S_LEN * HDIM];
__device__ __half g_Vh[S_LEN * HDIM];
__device__ __half g_VTh[HDIM * S_LEN];
__device__ __half g_O[S_LEN * HDIM];

// ---------------- helpers ----------------
__device__ __forceinline__ uint32_t smem_u32(const void* p) {
    uint32_t a;
    asm("{ .reg .u64 t; cvta.to.shared.u64 t, %1; cvt.u32.u64 %0, t; }"
        : "=r"(a) : "l"(p));
    return a;
}
__device__ __forceinline__ void ldsm4(uint32_t* r, uint32_t a) {
    asm volatile("ldmatrix.sync.aligned.m8n8.x4.shared.b16 {%0,%1,%2,%3}, [%4];"
        : "=r"(r[0]), "=r"(r[1]), "=r"(r[2]), "=r"(r[3]) : "r"(a));
}
__device__ __forceinline__ void mma_f16(float* c, const uint32_t* a,
                                        const uint32_t* b) {
    asm volatile("mma.sync.aligned.m16n8k16.row.col.f32.f16.f16.f32 "
        "{%0,%1,%2,%3}, {%4,%5,%6,%7}, {%8,%9}, {%0,%1,%2,%3};"
        : "+f"(c[0]), "+f"(c[1]), "+f"(c[2]), "+f"(c[3])
        : "r"(a[0]), "r"(a[1]), "r"(a[2]), "r"(a[3]), "r"(b[0]), "r"(b[1]));
}
__device__ __forceinline__ float ex2f(float x) {
    float r;
    asm("ex2.approx.f32 %0, %1;" : "=f"(r) : "f"(x));
    return r;
}
__device__ __forceinline__ void split_store2h(__half* hi, __half* lo,
                                              float x, float y) {
    __half hx = __float2half_rn(x), hy = __float2half_rn(y);
    __half2 h2 = __halves2half2(hx, hy);
    __half2 l2 = __halves2half2(__float2half_rn(x - __half2float(hx)),
                                __float2half_rn(y - __half2float(hy)));
    *reinterpret_cast<__half2*>(hi) = h2;
    *reinterpret_cast<__half2*>(lo) = l2;
}
__device__ __forceinline__ uint32_t pack2h(float x, float y) {
    __half hx = __float2half_rn(x), hy = __float2half_rn(y);
    uint16_t a = *(uint16_t*)&hx, b = *(uint16_t*)&hy;
    return (uint32_t)a | ((uint32_t)b << 16);
}
#define CP_ASYNC16(dst, src) \
    asm volatile("cp.async.cg.shared.global [%0], [%1], 16;\n" \
                 :: "r"(dst), "l"(src))
#define CP_COMMIT asm volatile("cp.async.commit_group;\n" ::: "memory")
#define CP_WAIT0  asm volatile("cp.async.wait_group 0;\n" ::: "memory")
#define CP_WAIT1  asm volatile("cp.async.wait_group 1;\n" ::: "memory")

// ---------------- prepass: fp32 -> fp16 ----------------
__global__ __launch_bounds__(256) void conv_fp16(
    const float* __restrict__ in, __half* __restrict__ out, int n4)
{
    int i = blockIdx.x * blockDim.x + threadIdx.x;
    if (i < n4) {
        float4 v = ((const float4*)in)[i];
        *(__half2*)(out + i * 4) =
            __halves2half2(__float2half_rn(v.x), __float2half_rn(v.y));
        *(__half2*)(out + i * 4 + 2) =
            __halves2half2(__float2half_rn(v.z), __float2half_rn(v.w));
    }
}
__global__ __launch_bounds__(256) void conv_fp16_w4(
    const float* __restrict__ w0, const float* __restrict__ w1,
    const float* __restrict__ w2, const float* __restrict__ w3,
    __half* __restrict__ o0, __half* __restrict__ o1,
    __half* __restrict__ o2, __half* __restrict__ o3, int n4)
{
    const float* src = (blockIdx.y == 0) ? w0 : (blockIdx.y == 1) ? w1
                       : (blockIdx.y == 2) ? w2 : w3;
    __half* dst = (blockIdx.y == 0) ? o0 : (blockIdx.y == 1) ? o1
                  : (blockIdx.y == 2) ? o2 : o3;
    int i = blockIdx.x * blockDim.x + threadIdx.x;
    if (i < n4) {
        float4 v = ((const float4*)src)[i];
        *(__half2*)(dst + i * 4) =
            __halves2half2(__float2half_rn(v.x), __float2half_rn(v.y));
        *(__half2*)(dst + i * 4 + 2) =
            __halves2half2(__float2half_rn(v.z), __float2half_rn(v.w));
    }
}

// ---- HMMA GEMM v4: BM=128 BN=256 BK=64, 256 threads (2x4 warps, 64x64 tile),
//      3-stage cp.async. Halved barrier count vs BK=32.
#define LDAB 72                        /* 64 + 8 halves                      */
#define G_BOFF 18432                   /* A plane bytes: 128*72*2            */
#define STG_BYTES 55296                /* A 18432 + B 36864                  */
#define GEMM_SMEM (3 * STG_BYTES)      /* 165888                             */

template <int OUT_MODE>
__global__ __launch_bounds__(256) void gemm_hmma(
    const __half* __restrict__ A, const __half* __restrict__ B,
    const float* __restrict__ bias, float scale,
    float* __restrict__ Cf, __half* __restrict__ Chh,
    __half* __restrict__ Chl, __half* __restrict__ Ch,
    int M, int N, int K)
{
    extern __shared__ char smraw[];
    const uint32_t sb = smem_u32(smraw);

    const int tid = threadIdx.x, lane = tid & 31, wid = tid >> 5;
    const int wm = wid >> 2, wn = wid & 3;           // 2 x 4 warps
    const int bm = blockIdx.y * 128, bn = blockIdx.x * 256;
    const int m0 = wm * 64, n0 = wn * 64;

    const int a_r = lane & 15, a_c = (lane >> 4) * 8;
    const int b_n = ((lane >> 4) & 1) * 8 + (lane & 7);
    const int b_k = ((lane >> 3) & 1) * 8;

    // loaders: row = tid>>1 (A: +0/+... ), 8 chunks per 64-wide row
    const int l_row = tid >> 1, l_col = (tid & 1) * 32;  // 2 thr/row, 32 halves each

    float acc[4][8][4];
#pragma unroll
    for (int mt = 0; mt < 4; mt++)
#pragma unroll
        for (int nt = 0; nt < 8; nt++)
#pragma unroll
            for (int j = 0; j < 4; j++) acc[mt][nt][j] = 0.f;

    const int nIter = K / 64;

    auto load_stage = [&](int kc, int s) {
        const uint32_t st = sb + s * STG_BYTES;
        const int k0 = kc * 64;
        // A: 128 rows x 64 cols, 2 threads per row, 4 chunks each
        {
            const __half* ap = A + (size_t)(bm + l_row) * K + k0 + l_col;
#pragma unroll
            for (int j = 0; j < 4; j++)
                CP_ASYNC16(st + (l_row * LDAB + l_col + j * 8) * 2, ap + j * 8);
        }
        // B: 256 rows x 64 cols, 2 threads per row covers 128 rows per pass, 2 passes
#pragma unroll
        for (int it = 0; it < 2; it++) {
            int row = l_row + it * 128;
            const __half* bp = B + (size_t)(bn + row) * K + k0 + l_col;
#pragma unroll
            for (int j = 0; j < 4; j++)
                CP_ASYNC16(st + G_BOFF + (row * LDAB + l_col + j * 8) * 2,
                           bp + j * 8);
        }
        CP_COMMIT;
    };

    load_stage(0, 0);
    load_stage(1, 1);
    for (int kc = 0; kc < nIter; kc++) {
        CP_WAIT1;
        __syncthreads();
        if (kc + 2 < nIter) load_stage(kc + 2, (kc + 2) % 3);

        const uint32_t st = sb + (kc % 3) * STG_BYTES;
#pragma unroll
        for (int ks = 0; ks < 4; ks++) {
            const int k0 = ks * 16;
            uint32_t ah[4][4], bb[4][4];
#pragma unroll
            for (int mt = 0; mt < 4; mt++) {
                int off = ((m0 + mt * 16 + a_r) * LDAB + k0 + a_c) * 2;
                ldsm4(ah[mt], st + off);
            }
#pragma unroll
            for (int bp = 0; bp < 4; bp++) {
                int off = ((n0 + bp * 16 + b_n) * LDAB + k0 + b_k) * 2;
                ldsm4(bb[bp], st + G_BOFF + off);
            }
#pragma unroll
            for (int mt = 0; mt < 4; mt++)
#pragma unroll
                for (int nt = 0; nt < 8; nt++)
                    mma_f16(acc[mt][nt], ah[mt], &bb[nt >> 1][(nt & 1) * 2]);
        }
    }

#pragma unroll
    for (int mt = 0; mt < 4; mt++) {
        const int r0 = bm + m0 + mt * 16 + (lane >> 2);
#pragma unroll
        for (int nt = 0; nt < 8; nt++) {
            const int col = bn + n0 + nt * 8 + (lane & 3) * 2;
            float2 bv = *(const float2*)(bias + col);
            float c00 = (acc[mt][nt][0] + bv.x) * scale;
            float c01 = (acc[mt][nt][1] + bv.y) * scale;
            float c10 = (acc[mt][nt][2] + bv.x) * scale;
            float c11 = (acc[mt][nt][3] + bv.y) * scale;
            if (OUT_MODE == 0) {
                *(float2*)(Cf + (size_t)r0 * N + col) = make_float2(c00, c01);
                *(float2*)(Cf + (size_t)(r0 + 8) * N + col) = make_float2(c10, c11);
            } else if (OUT_MODE == 1) {
                split_store2h(Chh + (size_t)r0 * N + col,
                              Chl + (size_t)r0 * N + col, c00, c01);
                split_store2h(Chh + (size_t)(r0 + 8) * N + col,
                              Chl + (size_t)(r0 + 8) * N + col, c10, c11);
            } else {
                *(uint32_t*)(Ch + (size_t)r0 * N + col) = pack2h(c00, c01);
                *(uint32_t*)(Ch + (size_t)(r0 + 8) * N + col) = pack2h(c10, c11);
            }
        }
    }
}

// ------- transpose fp16: out[c][s] = in[s][c] -------
__global__ __launch_bounds__(256) void transpose_h(
    const __half* __restrict__ in, __half* __restrict__ out)
{
    __shared__ __half tile[32][34];
    const int cb = blockIdx.x * 32, sbk = blockIdx.y * 32;
    const int tx = threadIdx.x, ty = threadIdx.y;
#pragma unroll
    for (int j = 0; j < 4; j++)
        tile[ty + j * 8][tx] = in[(size_t)(sbk + ty + j * 8) * HDIM + cb + tx];
    __syncthreads();
#pragma unroll
    for (int j = 0; j < 4; j++)
        out[(size_t)(cb + ty + j * 8) * S_LEN + sbk + tx] = tile[tx][ty + j * 8];
}

// ---------------- fp16 flash attention (round-14 champion, unchanged) ----
#define LDQ 136
#define LDV 72
#define AQL 17408
#define ASTG0 34816
#define ASTG  17920
#define AVH_OFF 8704
#define ATT_SMEM 141312

__global__ __launch_bounds__(256) void attn_hmma(
    const __half* __restrict__ Qhi, const __half* __restrict__ Qlo,
    const __half* __restrict__ Kh, const __half* __restrict__ VTh,
    __half* __restrict__ O)
{
    extern __shared__ __half smh[];
    const uint32_t sb = smem_u32(smh);

    const int tid = threadIdx.x, lane = tid & 31, wid = tid >> 5;
    const int qb = blockIdx.x * 128, h = blockIdx.y;

    const int a_r = lane & 15, a_c = (lane >> 4) * 8;
    const int b_n = ((lane >> 4) & 1) * 8 + (lane & 7);
    const int b_k = ((lane >> 3) & 1) * 8;
    const int qrow = wid * 16;

    const int k_r = tid >> 2, k_c = (tid & 3) * 32;
    const int v_r = tid >> 1, v_c = (tid & 1) * 32;

    auto load_kv = [&](int t, int s) {
        const uint32_t stg = sb + (ASTG0 + s * ASTG) * 2;
        const __half* kp = Kh + (size_t)(t * 64 + k_r) * HDIM + h * HD + k_c;
#pragma unroll
        for (int j = 0; j < 4; j++)
            CP_ASYNC16(stg + (k_r * LDQ + k_c + j * 8) * 2, kp + j * 8);
        const __half* vp = VTh + (size_t)(h * HD + v_r) * S_LEN + t * 64 + v_c;
#pragma unroll
        for (int j = 0; j < 4; j++)
            CP_ASYNC16(stg + (AVH_OFF + v_r * LDV + v_c + j * 8) * 2, vp + j * 8);
        CP_COMMIT;
    };

    {
        const int r = tid >> 1, cs = (tid & 1) * 64;
        const __half* qh = Qhi + (size_t)(qb + r) * HDIM + h * HD + cs;
        const __half* ql = Qlo + (size_t)(qb + r) * HDIM + h * HD + cs;
#pragma unroll
        for (int j = 0; j < 8; j++) {
            CP_ASYNC16(sb + (r * LDQ + cs + j * 8) * 2, qh + j * 8);
            CP_ASYNC16(sb + (AQL + r * LDQ + cs + j * 8) * 2, ql + j * 8);
        }
        CP_COMMIT;          // group: Q
    }
    load_kv(0, 0);          // group: KV(0)

    CP_WAIT1;
    __syncthreads();

    uint32_t qfh[8][4], qfl[8][4];
#pragma unroll
    for (int ks = 0; ks < 8; ks++) {
        int off = ((qrow + a_r) * LDQ + ks * 16 + a_c) * 2;
        ldsm4(qfh[ks], sb + off);
        ldsm4(qfl[ks], sb + AQL * 2 + off);
    }

    float m0 = -INFINITY, m1 = -INFINITY, l0 = 0.f, l1 = 0.f;
    float oacc[16][4];
#pragma unroll
    for (int nt = 0; nt < 16; nt++)
#pragma unroll
        for (int j = 0; j < 4; j++) oacc[nt][j] = 0.f;

    const int NT = S_LEN / 64;
    for (int t = 0; t < NT; t++) {
        const int s = t & 1;
        CP_WAIT0;
        __syncthreads();
        if (t + 1 < NT) load_kv(t + 1, s ^ 1);

        const uint32_t stg = sb + (ASTG0 + s * ASTG) * 2;

        // ---- Phase 1: S = Q K^T (2 MMAs, Q hi/lo exact) ----
        float sacc[8][4];
#pragma unroll
        for (int nt = 0; nt < 8; nt++)
#pragma unroll
            for (int j = 0; j < 4; j++) sacc[nt][j] = 0.f;

#pragma unroll
        for (int ks = 0; ks < 8; ks++) {
            const int k0 = ks * 16;
            uint32_t bh[4][4];
#pragma unroll
            for (int g = 0; g < 4; g++) {
                int off = ((g * 16 + b_n) * LDQ + k0 + b_k) * 2;
                ldsm4(bh[g], stg + off);
            }
#pragma unroll
            for (int nt = 0; nt < 8; nt++) {
                const uint32_t* bhp = &bh[nt >> 1][(nt & 1) * 2];
                mma_f16(sacc[nt], qfh[ks], bhp);
                mma_f16(sacc[nt], qfl[ks], bhp);
            }
        }

        // ---- warp-local online softmax (log2 domain) ----
        float tm0 = -INFINITY, tm1 = -INFINITY;
#pragma unroll
        for (int nt = 0; nt < 8; nt++) {
            tm0 = fmaxf(tm0, fmaxf(sacc[nt][0], sacc[nt][1]));
            tm1 = fmaxf(tm1, fmaxf(sacc[nt][2], sacc[nt][3]));
        }
        tm0 = fmaxf(tm0, __shfl_xor_sync(0xffffffffu, tm0, 1));
        tm0 = fmaxf(tm0, __shfl_xor_sync(0xffffffffu, tm0, 2));
        tm1 = fmaxf(tm1, __shfl_xor_sync(0xffffffffu, tm1, 1));
        tm1 = fmaxf(tm1, __shfl_xor_sync(0xffffffffu, tm1, 2));
        const float mn0 = fmaxf(m0, tm0), mn1 = fmaxf(m1, tm1);
        const float c0 = ex2f(m0 - mn0), c1 = ex2f(m1 - mn1);
        m0 = mn0; m1 = mn1;

        float ls0 = 0.f, ls1 = 0.f;
#pragma unroll
        for (int nt = 0; nt < 8; nt++) {
            sacc[nt][0] = ex2f(sacc[nt][0] - mn0);
            sacc[nt][1] = ex2f(sacc[nt][1] - mn0);
            sacc[nt][2] = ex2f(sacc[nt][2] - mn1);
            sacc[nt][3] = ex2f(sacc[nt][3] - mn1);
            ls0 += sacc[nt][0] + sacc[nt][1];
            ls1 += sacc[nt][2] + sacc[nt][3];
        }
        ls0 += __shfl_xor_sync(0xffffffffu, ls0, 1);
        ls0 += __shfl_xor_sync(0xffffffffu, ls0, 2);
        ls1 += __shfl_xor_sync(0xffffffffu, ls1, 1);
        ls1 += __shfl_xor_sync(0xffffffffu, ls1, 2);
        l0 = l0 * c0 + ls0;
        l1 = l1 * c1 + ls1;

        if (c0 != 1.f || c1 != 1.f) {
#pragma unroll
            for (int nt = 0; nt < 16; nt++) {
                oacc[nt][0] *= c0; oacc[nt][1] *= c0;
                oacc[nt][2] *= c1; oacc[nt][3] *= c1;
            }
        }

        // ---- Phase 2: O += P V (single fp16 P) ----
#pragma unroll
        for (int ks = 0; ks < 4; ks++) {
            uint32_t p4[4];
            p4[0] = pack2h(sacc[2 * ks][0], sacc[2 * ks][1]);
            p4[1] = pack2h(sacc[2 * ks][2], sacc[2 * ks][3]);
            p4[2] = pack2h(sacc[2 * ks + 1][0], sacc[2 * ks + 1][1]);
            p4[3] = pack2h(sacc[2 * ks + 1][2], sacc[2 * ks + 1][3]);
            const int k0 = ks * 16;
#pragma unroll
            for (int g = 0; g < 8; g++) {
                uint32_t vh[4];
                int off = ((g * 16 + b_n) * LDV + k0 + b_k) * 2;
                ldsm4(vh, stg + AVH_OFF * 2 + off);
                mma_f16(oacc[g * 2 + 0], p4, &vh[0]);
                mma_f16(oacc[g * 2 + 1], p4, &vh[2]);
            }
        }
    }

    // ---- epilogue ----
    const float inv0 = 1.f / l0, inv1 = 1.f / l1;
    const int r0 = qrow + (lane >> 2);
#pragma unroll
    for (int nt = 0; nt < 16; nt++) {
        const int col = nt * 8 + (lane & 3) * 2;
        size_t i0 = (size_t)(qb + r0) * HDIM + h * HD + col;
        size_t i1 = (size_t)(qb + r0 + 8) * HDIM + h * HD + col;
        *(uint32_t*)(O + i0) = pack2h(oacc[nt][0] * inv0, oacc[nt][1] * inv0);
        *(uint32_t*)(O + i1) = pack2h(oacc[nt][2] * inv1, oacc[nt][3] * inv1);
    }
}

// ---------------- launch ----------------
extern "C" void kernel_launch(void* const* d_in, const int* in_sizes, int n_in,
                              void* d_out, int out_size)
{
    const float* hidden = (const float*)d_in[0];
    const float* Wq = (const float*)d_in[1];
    const float* bq = (const float*)d_in[2];
    const float* Wk = (const float*)d_in[3];
    const float* bk = (const float*)d_in[4];
    const float* Wv = (const float*)d_in[5];
    const float* bv = (const float*)d_in[6];
    const float* Wo = (const float*)d_in[7];
    const float* bo = (const float*)d_in[8];
    float* out = (float*)d_out;

    __half *Hp, *Wqp, *Wkp, *Wvp, *Wop, *Qh, *Ql, *Kh, *Vh, *VTh, *Op;
    cudaGetSymbolAddress((void**)&Hp, g_H);
    cudaGetSymbolAddress((void**)&Wqp, g_Wq);   cudaGetSymbolAddress((void**)&Wkp, g_Wk);
    cudaGetSymbolAddress((void**)&Wvp, g_Wv);   cudaGetSymbolAddress((void**)&Wop, g_Wo);
    cudaGetSymbolAddress((void**)&Qh, g_Qh);    cudaGetSymbolAddress((void**)&Ql, g_Ql);
    cudaGetSymbolAddress((void**)&Kh, g_Kh);    cudaGetSymbolAddress((void**)&Vh, g_Vh);
    cudaGetSymbolAddress((void**)&VTh, g_VTh);
    cudaGetSymbolAddress((void**)&Op, g_O);

    cudaFuncSetAttribute(gemm_hmma<0>, cudaFuncAttributeMaxDynamicSharedMemorySize, GEMM_SMEM);
    cudaFuncSetAttribute(gemm_hmma<1>, cudaFuncAttributeMaxDynamicSharedMemorySize, GEMM_SMEM);
    cudaFuncSetAttribute(gemm_hmma<2>, cudaFuncAttributeMaxDynamicSharedMemorySize, GEMM_SMEM);
    cudaFuncSetAttribute(attn_hmma, cudaFuncAttributeMaxDynamicSharedMemorySize, ATT_SMEM);

    const int nH4 = S_LEN * HDIM / 4, nW4 = HDIM * HDIM / 4;
    conv_fp16<<<nH4 / 256, 256>>>(hidden, Hp, nH4);
    conv_fp16_w4<<<dim3(nW4 / 256, 4), 256>>>(Wq, Wk, Wv, Wo,
                                              Wqp, Wkp, Wvp, Wop, nW4);

    dim3 ggrid(HDIM / 256, S_LEN / 128);   // (8, 32) = 256 CTAs
    gemm_hmma<1><<<ggrid, 256, GEMM_SMEM>>>(Hp, Wqp, bq, SCALE2,
                                            nullptr, Qh, Ql, nullptr,
                                            S_LEN, HDIM, HDIM);
    gemm_hmma<2><<<ggrid, 256, GEMM_SMEM>>>(Hp, Wkp, bk, 1.f,
                                            nullptr, nullptr, nullptr, Kh,
                                            S_LEN, HDIM, HDIM);
    gemm_hmma<2><<<ggrid, 256, GEMM_SMEM>>>(Hp, Wvp, bv, 1.f,
                                            nullptr, nullptr, nullptr, Vh,
                                            S_LEN, HDIM, HDIM);

    dim3 tgrid(HDIM / 32, S_LEN / 32);
    transpose_h<<<tgrid, dim3(32, 8)>>>(Vh, VTh);

    dim3 agrid(S_LEN / 128, NHEADS);       // (32, 16)
    attn_hmma<<<agrid, 256, ATT_SMEM>>>(Qh, Ql, Kh, VTh, Op);

    gemm_hmma<0><<<ggrid, 256, GEMM_SMEM>>>(Op, Wop, bo, 1.f,
                                            out, nullptr, nullptr, nullptr,
                                            S_LEN, HDIM, HDIM);
}

// round 17
// speedup vs baseline: 1.2877x; 1.1535x over previous
#include <cuda_runtime.h>
#include <cuda_bf16.h>
#include <cuda_fp16.h>
#include <cstdint>
#include <math.h>

#define S_LEN 4096
#define HDIM  2048
#define NHEADS 16
#define HD    128
#define SCALE 0.08838834764831845f
#define SCALE2 0.1275332511737922f   // SCALE * log2(e)

// ---------------- scratch globals ----------------
__device__ __half g_H[S_LEN * HDIM];
__device__ __half g_Wq[HDIM * HDIM], g_Wk[HDIM * HDIM];
__device__ __half g_Wv[HDIM * HDIM], g_Wo[HDIM * HDIM];
__device__ __half g_Qh[S_LEN * HDIM];
__device__ __half g_Kh[S_LEN * HDIM];
__device__ __half g_Vh[S_LEN * HDIM];
__device__ __half g_VTh[HDIM * S_LEN];
__device__ __half g_O[S_LEN * HDIM];

// ---------------- helpers ----------------
__device__ __forceinline__ uint32_t smem_u32(const void* p) {
    uint32_t a;
    asm("{ .reg .u64 t; cvta.to.shared.u64 t, %1; cvt.u32.u64 %0, t; }"
        : "=r"(a) : "l"(p));
    return a;
}
__device__ __forceinline__ void ldsm4(uint32_t* r, uint32_t a) {
    asm volatile("ldmatrix.sync.aligned.m8n8.x4.shared.b16 {%0,%1,%2,%3}, [%4];"
        : "=r"(r[0]), "=r"(r[1]), "=r"(r[2]), "=r"(r[3]) : "r"(a));
}
__device__ __forceinline__ void mma_f16(float* c, const uint32_t* a,
                                        const uint32_t* b) {
    asm volatile("mma.sync.aligned.m16n8k16.row.col.f32.f16.f16.f32 "
        "{%0,%1,%2,%3}, {%4,%5,%6,%7}, {%8,%9}, {%0,%1,%2,%3};"
        : "+f"(c[0]), "+f"(c[1]), "+f"(c[2]), "+f"(c[3])
        : "r"(a[0]), "r"(a[1]), "r"(a[2]), "r"(a[3]), "r"(b[0]), "r"(b[1]));
}
__device__ __forceinline__ float ex2f(float x) {
    float r;
    asm("ex2.approx.f32 %0, %1;" : "=f"(r) : "f"(x));
    return r;
}
__device__ __forceinline__ uint32_t pack2h(float x, float y) {
    __half hx = __float2half_rn(x), hy = __float2half_rn(y);
    uint16_t a = *(uint16_t*)&hx, b = *(uint16_t*)&hy;
    return (uint32_t)a | ((uint32_t)b << 16);
}
#define CP_ASYNC16(dst, src) \
    asm volatile("cp.async.cg.shared.global [%0], [%1], 16;\n" \
                 :: "r"(dst), "l"(src))
#define CP_COMMIT asm volatile("cp.async.commit_group;\n" ::: "memory")
#define CP_WAIT0  asm volatile("cp.async.wait_group 0;\n" ::: "memory")
#define CP_WAIT1  asm volatile("cp.async.wait_group 1;\n" ::: "memory")

// ---------------- prepass: fp32 -> fp16 ----------------
__global__ __launch_bounds__(256) void conv_fp16(
    const float* __restrict__ in, __half* __restrict__ out, int n4)
{
    int i = blockIdx.x * blockDim.x + threadIdx.x;
    if (i < n4) {
        float4 v = ((const float4*)in)[i];
        *(__half2*)(out + i * 4) =
            __halves2half2(__float2half_rn(v.x), __float2half_rn(v.y));
        *(__half2*)(out + i * 4 + 2) =
            __halves2half2(__float2half_rn(v.z), __float2half_rn(v.w));
    }
}
__global__ __launch_bounds__(256) void conv_fp16_w4(
    const float* __restrict__ w0, const float* __restrict__ w1,
    const float* __restrict__ w2, const float* __restrict__ w3,
    __half* __restrict__ o0, __half* __restrict__ o1,
    __half* __restrict__ o2, __half* __restrict__ o3, int n4)
{
    const float* src = (blockIdx.y == 0) ? w0 : (blockIdx.y == 1) ? w1
                       : (blockIdx.y == 2) ? w2 : w3;
    __half* dst = (blockIdx.y == 0) ? o0 : (blockIdx.y == 1) ? o1
                  : (blockIdx.y == 2) ? o2 : o3;
    int i = blockIdx.x * blockDim.x + threadIdx.x;
    if (i < n4) {
        float4 v = ((const float4*)src)[i];
        *(__half2*)(dst + i * 4) =
            __halves2half2(__float2half_rn(v.x), __float2half_rn(v.y));
        *(__half2*)(dst + i * 4 + 2) =
            __halves2half2(__float2half_rn(v.z), __float2half_rn(v.w));
    }
}

// ---- HMMA GEMM (round-14 champion): BM=128 BN=256 BK=32, 256 thr,
//      warp tile 64x64, 3-stage cp.async.
// OUT_MODE: 0 = fp32, 2 = fp16 single plane
#define LDAB 40
#define G_BOFF 10240
#define STG_BYTES 30720
#define GEMM_SMEM (3 * STG_BYTES)

template <int OUT_MODE>
__global__ __launch_bounds__(256) void gemm_hmma(
    const __half* __restrict__ A, const __half* __restrict__ B,
    const float* __restrict__ bias, float scale,
    float* __restrict__ Cf, __half* __restrict__ Ch,
    int M, int N, int K)
{
    extern __shared__ char smraw[];
    const uint32_t sb = smem_u32(smraw);

    const int tid = threadIdx.x, lane = tid & 31, wid = tid >> 5;
    const int wm = wid >> 2, wn = wid & 3;
    const int bm = blockIdx.y * 128, bn = blockIdx.x * 256;
    const int m0 = wm * 64, n0 = wn * 64;

    const int a_r = lane & 15, a_c = (lane >> 4) * 8;
    const int b_n = ((lane >> 4) & 1) * 8 + (lane & 7);
    const int b_k = ((lane >> 3) & 1) * 8;

    const int l_row = tid >> 2, l_col = (tid & 3) * 8;

    float acc[4][8][4];
#pragma unroll
    for (int mt = 0; mt < 4; mt++)
#pragma unroll
        for (int nt = 0; nt < 8; nt++)
#pragma unroll
            for (int j = 0; j < 4; j++) acc[mt][nt][j] = 0.f;

    const int nIter = K / 32;

    auto load_stage = [&](int kc, int s) {
        const uint32_t st = sb + s * STG_BYTES;
        const int k0 = kc * 32;
#pragma unroll
        for (int it = 0; it < 2; it++) {
            int row = l_row + it * 64;
            CP_ASYNC16(st + (row * LDAB + l_col) * 2,
                       A + (size_t)(bm + row) * K + k0 + l_col);
        }
#pragma unroll
        for (int it = 0; it < 4; it++) {
            int row = l_row + it * 64;
            CP_ASYNC16(st + G_BOFF + (row * LDAB + l_col) * 2,
                       B + (size_t)(bn + row) * K + k0 + l_col);
        }
        CP_COMMIT;
    };

    load_stage(0, 0);
    load_stage(1, 1);
    for (int kc = 0; kc < nIter; kc++) {
        CP_WAIT1;
        __syncthreads();
        if (kc + 2 < nIter) load_stage(kc + 2, (kc + 2) % 3);

        const uint32_t st = sb + (kc % 3) * STG_BYTES;
#pragma unroll
        for (int ks = 0; ks < 2; ks++) {
            const int k0 = ks * 16;
            uint32_t ah[4][4], bb[4][4];
#pragma unroll
            for (int mt = 0; mt < 4; mt++) {
                int off = ((m0 + mt * 16 + a_r) * LDAB + k0 + a_c) * 2;
                ldsm4(ah[mt], st + off);
            }
#pragma unroll
            for (int bp = 0; bp < 4; bp++) {
                int off = ((n0 + bp * 16 + b_n) * LDAB + k0 + b_k) * 2;
                ldsm4(bb[bp], st + G_BOFF + off);
            }
#pragma unroll
            for (int mt = 0; mt < 4; mt++)
#pragma unroll
                for (int nt = 0; nt < 8; nt++)
                    mma_f16(acc[mt][nt], ah[mt], &bb[nt >> 1][(nt & 1) * 2]);
        }
    }

#pragma unroll
    for (int mt = 0; mt < 4; mt++) {
        const int r0 = bm + m0 + mt * 16 + (lane >> 2);
#pragma unroll
        for (int nt = 0; nt < 8; nt++) {
            const int col = bn + n0 + nt * 8 + (lane & 3) * 2;
            float2 bv = *(const float2*)(bias + col);
            float c00 = (acc[mt][nt][0] + bv.x) * scale;
            float c01 = (acc[mt][nt][1] + bv.y) * scale;
            float c10 = (acc[mt][nt][2] + bv.x) * scale;
            float c11 = (acc[mt][nt][3] + bv.y) * scale;
            if (OUT_MODE == 0) {
                *(float2*)(Cf + (size_t)r0 * N + col) = make_float2(c00, c01);
                *(float2*)(Cf + (size_t)(r0 + 8) * N + col) = make_float2(c10, c11);
            } else {
                *(uint32_t*)(Ch + (size_t)r0 * N + col) = pack2h(c00, c01);
                *(uint32_t*)(Ch + (size_t)(r0 + 8) * N + col) = pack2h(c10, c11);
            }
        }
    }
}

// ------- transpose fp16: out[c][s] = in[s][c] -------
__global__ __launch_bounds__(256) void transpose_h(
    const __half* __restrict__ in, __half* __restrict__ out)
{
    __shared__ __half tile[32][34];
    const int cb = blockIdx.x * 32, sbk = blockIdx.y * 32;
    const int tx = threadIdx.x, ty = threadIdx.y;
#pragma unroll
    for (int j = 0; j < 4; j++)
        tile[ty + j * 8][tx] = in[(size_t)(sbk + ty + j * 8) * HDIM + cb + tx];
    __syncthreads();
#pragma unroll
    for (int j = 0; j < 4; j++)
        out[(size_t)(cb + ty + j * 8) * S_LEN + sbk + tx] = tile[tx][ty + j * 8];
}

// ---------------- fp16 flash attention: Q single fp16 in registers --------
// S = Q·K (1 MMA), O += P·V (1 MMA). ex2 softmax (log2 domain).
// smem (elems): Q 0 (128*136=17408) | stage s at 17408 + s*17920:
//   K +0 (8704), V +8704 (9216). Total (17408 + 2*17920)*2 = 106496 B.
#define LDQ 136
#define LDV 72
#define ASTG0 17408
#define ASTG  17920
#define AVH_OFF 8704
#define ATT_SMEM 106496

__global__ __launch_bounds__(256) void attn_hmma(
    const __half* __restrict__ Qg, const __half* __restrict__ Kh,
    const __half* __restrict__ VTh, __half* __restrict__ O)
{
    extern __shared__ __half smh[];
    const uint32_t sb = smem_u32(smh);

    const int tid = threadIdx.x, lane = tid & 31, wid = tid >> 5;
    const int qb = blockIdx.x * 128, h = blockIdx.y;

    const int a_r = lane & 15, a_c = (lane >> 4) * 8;
    const int b_n = ((lane >> 4) & 1) * 8 + (lane & 7);
    const int b_k = ((lane >> 3) & 1) * 8;
    const int qrow = wid * 16;

    const int k_r = tid >> 2, k_c = (tid & 3) * 32;
    const int v_r = tid >> 1, v_c = (tid & 1) * 32;

    auto load_kv = [&](int t, int s) {
        const uint32_t stg = sb + (ASTG0 + s * ASTG) * 2;
        const __half* kp = Kh + (size_t)(t * 64 + k_r) * HDIM + h * HD + k_c;
#pragma unroll
        for (int j = 0; j < 4; j++)
            CP_ASYNC16(stg + (k_r * LDQ + k_c + j * 8) * 2, kp + j * 8);
        const __half* vp = VTh + (size_t)(h * HD + v_r) * S_LEN + t * 64 + v_c;
#pragma unroll
        for (int j = 0; j < 4; j++)
            CP_ASYNC16(stg + (AVH_OFF + v_r * LDV + v_c + j * 8) * 2, vp + j * 8);
        CP_COMMIT;
    };

    // Q tile (single fp16 plane, pre-scaled by SCALE2 in projection)
    {
        const int r = tid >> 1, cs = (tid & 1) * 64;
        const __half* qp = Qg + (size_t)(qb + r) * HDIM + h * HD + cs;
#pragma unroll
        for (int j = 0; j < 8; j++)
            CP_ASYNC16(sb + (r * LDQ + cs + j * 8) * 2, qp + j * 8);
        CP_COMMIT;          // group: Q
    }
    load_kv(0, 0);          // group: KV(0)

    CP_WAIT1;
    __syncthreads();

    uint32_t qf[8][4];
#pragma unroll
    for (int ks = 0; ks < 8; ks++) {
        int off = ((qrow + a_r) * LDQ + ks * 16 + a_c) * 2;
        ldsm4(qf[ks], sb + off);
    }

    float m0 = -INFINITY, m1 = -INFINITY, l0 = 0.f, l1 = 0.f;
    float oacc[16][4];
#pragma unroll
    for (int nt = 0; nt < 16; nt++)
#pragma unroll
        for (int j = 0; j < 4; j++) oacc[nt][j] = 0.f;

    const int NT = S_LEN / 64;
    for (int t = 0; t < NT; t++) {
        const int s = t & 1;
        CP_WAIT0;
        __syncthreads();
        if (t + 1 < NT) load_kv(t + 1, s ^ 1);

        const uint32_t stg = sb + (ASTG0 + s * ASTG) * 2;

        // ---- Phase 1: S = Q K^T (1 MMA per sub-tile) ----
        float sacc[8][4];
#pragma unroll
        for (int nt = 0; nt < 8; nt++)
#pragma unroll
            for (int j = 0; j < 4; j++) sacc[nt][j] = 0.f;

#pragma unroll
        for (int ks = 0; ks < 8; ks++) {
            const int k0 = ks * 16;
            uint32_t bh[4][4];
#pragma unroll
            for (int g = 0; g < 4; g++) {
                int off = ((g * 16 + b_n) * LDQ + k0 + b_k) * 2;
                ldsm4(bh[g], stg + off);
            }
#pragma unroll
            for (int nt = 0; nt < 8; nt++)
                mma_f16(sacc[nt], qf[ks], &bh[nt >> 1][(nt & 1) * 2]);
        }

        // ---- warp-local online softmax (log2 domain) ----
        float tm0 = -INFINITY, tm1 = -INFINITY;
#pragma unroll
        for (int nt = 0; nt < 8; nt++) {
            tm0 = fmaxf(tm0, fmaxf(sacc[nt][0], sacc[nt][1]));
            tm1 = fmaxf(tm1, fmaxf(sacc[nt][2], sacc[nt][3]));
        }
        tm0 = fmaxf(tm0, __shfl_xor_sync(0xffffffffu, tm0, 1));
        tm0 = fmaxf(tm0, __shfl_xor_sync(0xffffffffu, tm0, 2));
        tm1 = fmaxf(tm1, __shfl_xor_sync(0xffffffffu, tm1, 1));
        tm1 = fmaxf(tm1, __shfl_xor_sync(0xffffffffu, tm1, 2));
        const float mn0 = fmaxf(m0, tm0), mn1 = fmaxf(m1, tm1);
        const float c0 = ex2f(m0 - mn0), c1 = ex2f(m1 - mn1);
        m0 = mn0; m1 = mn1;

        float ls0 = 0.f, ls1 = 0.f;
#pragma unroll
        for (int nt = 0; nt < 8; nt++) {
            sacc[nt][0] = ex2f(sacc[nt][0] - mn0);
            sacc[nt][1] = ex2f(sacc[nt][1] - mn0);
            sacc[nt][2] = ex2f(sacc[nt][2] - mn1);
            sacc[nt][3] = ex2f(sacc[nt][3] - mn1);
            ls0 += sacc[nt][0] + sacc[nt][1];
            ls1 += sacc[nt][2] + sacc[nt][3];
        }
        ls0 += __shfl_xor_sync(0xffffffffu, ls0, 1);
        ls0 += __shfl_xor_sync(0xffffffffu, ls0, 2);
        ls1 += __shfl_xor_sync(0xffffffffu, ls1, 1);
        ls1 += __shfl_xor_sync(0xffffffffu, ls1, 2);
        l0 = l0 * c0 + ls0;
        l1 = l1 * c1 + ls1;

        if (c0 != 1.f || c1 != 1.f) {
#pragma unroll
            for (int nt = 0; nt < 16; nt++) {
                oacc[nt][0] *= c0; oacc[nt][1] *= c0;
                oacc[nt][2] *= c1; oacc[nt][3] *= c1;
            }
        }

        // ---- Phase 2: O += P V (single fp16 P) ----
#pragma unroll
        for (int ks = 0; ks < 4; ks++) {
            uint32_t p4[4];
            p4[0] = pack2h(sacc[2 * ks][0], sacc[2 * ks][1]);
            p4[1] = pack2h(sacc[2 * ks][2], sacc[2 * ks][3]);
            p4[2] = pack2h(sacc[2 * ks + 1][0], sacc[2 * ks + 1][1]);
            p4[3] = pack2h(sacc[2 * ks + 1][2], sacc[2 * ks + 1][3]);
            const int k0 = ks * 16;
#pragma unroll
            for (int g = 0; g < 8; g++) {
                uint32_t vh[4];
                int off = ((g * 16 + b_n) * LDV + k0 + b_k) * 2;
                ldsm4(vh, stg + AVH_OFF * 2 + off);
                mma_f16(oacc[g * 2 + 0], p4, &vh[0]);
                mma_f16(oacc[g * 2 + 1], p4, &vh[2]);
            }
        }
    }

    // ---- epilogue ----
    const float inv0 = 1.f / l0, inv1 = 1.f / l1;
    const int r0 = qrow + (lane >> 2);
#pragma unroll
    for (int nt = 0; nt < 16; nt++) {
        const int col = nt * 8 + (lane & 3) * 2;
        size_t i0 = (size_t)(qb + r0) * HDIM + h * HD + col;
        size_t i1 = (size_t)(qb + r0 + 8) * HDIM + h * HD + col;
        *(uint32_t*)(O + i0) = pack2h(oacc[nt][0] * inv0, oacc[nt][1] * inv0);
        *(uint32_t*)(O + i1) = pack2h(oacc[nt][2] * inv1, oacc[nt][3] * inv1);
    }
}

// ---------------- launch ----------------
extern "C" void kernel_launch(void* const* d_in, const int* in_sizes, int n_in,
                              void* d_out, int out_size)
{
    const float* hidden = (const float*)d_in[0];
    const float* Wq = (const float*)d_in[1];
    const float* bq = (const float*)d_in[2];
    const float* Wk = (const float*)d_in[3];
    const float* bk = (const float*)d_in[4];
    const float* Wv = (const float*)d_in[5];
    const float* bv = (const float*)d_in[6];
    const float* Wo = (const float*)d_in[7];
    const float* bo = (const float*)d_in[8];
    float* out = (float*)d_out;

    __half *Hp, *Wqp, *Wkp, *Wvp, *Wop, *Qh, *Kh, *Vh, *VTh, *Op;
    cudaGetSymbolAddress((void**)&Hp, g_H);
    cudaGetSymbolAddress((void**)&Wqp, g_Wq);   cudaGetSymbolAddress((void**)&Wkp, g_Wk);
    cudaGetSymbolAddress((void**)&Wvp, g_Wv);   cudaGetSymbolAddress((void**)&Wop, g_Wo);
    cudaGetSymbolAddress((void**)&Qh, g_Qh);
    cudaGetSymbolAddress((void**)&Kh, g_Kh);    cudaGetSymbolAddress((void**)&Vh, g_Vh);
    cudaGetSymbolAddress((void**)&VTh, g_VTh);
    cudaGetSymbolAddress((void**)&Op, g_O);

    cudaFuncSetAttribute(gemm_hmma<0>, cudaFuncAttributeMaxDynamicSharedMemorySize, GEMM_SMEM);
    cudaFuncSetAttribute(gemm_hmma<2>, cudaFuncAttributeMaxDynamicSharedMemorySize, GEMM_SMEM);
    cudaFuncSetAttribute(attn_hmma, cudaFuncAttributeMaxDynamicSharedMemorySize, ATT_SMEM);

    const int nH4 = S_LEN * HDIM / 4, nW4 = HDIM * HDIM / 4;
    conv_fp16<<<nH4 / 256, 256>>>(hidden, Hp, nH4);
    conv_fp16_w4<<<dim3(nW4 / 256, 4), 256>>>(Wq, Wk, Wv, Wo,
                                              Wqp, Wkp, Wvp, Wop, nW4);

    dim3 ggrid(HDIM / 256, S_LEN / 128);   // (8, 32)
    gemm_hmma<2><<<ggrid, 256, GEMM_SMEM>>>(Hp, Wqp, bq, SCALE2,
                                            nullptr, Qh, S_LEN, HDIM, HDIM);
    gemm_hmma<2><<<ggrid, 256, GEMM_SMEM>>>(Hp, Wkp, bk, 1.f,
                                            nullptr, Kh, S_LEN, HDIM, HDIM);
    gemm_hmma<2><<<ggrid, 256, GEMM_SMEM>>>(Hp, Wvp, bv, 1.f,
                                            nullptr, Vh, S_LEN, HDIM, HDIM);

    dim3 tgrid(HDIM / 32, S_LEN / 32);
    transpose_h<<<tgrid, dim3(32, 8)>>>(Vh, VTh);

    dim3 agrid(S_LEN / 128, NHEADS);       // (32, 16)
    attn_hmma<<<agrid, 256, ATT_SMEM>>>(Qh, Kh, VTh, Op);

    gemm_hmma<0><<<ggrid, 256, GEMM_SMEM>>>(Op, Wop, bo, 1.f,
                                            out, nullptr, S_LEN, HDIM, HDIM);
}